// round 14
// baseline (speedup 1.0000x reference)
#include <cuda_runtime.h>
#include <cuda_fp16.h>
#include <cstdint>

#define BDIM   8192
#define IN_F   512
#define OUT_F  1024
#define K_TOT  1536
#define BM 128
#define BN 64
#define BK 128
#define NIT (K_TOT/BK)         // 12
#define A_STAGE 32768
#define B_STAGE 16384
#define SM_B_OFF (2*A_STAGE)
#define SMEM_DYN (2*A_STAGE + 2*B_STAGE + 1024)
#define NTILES 1024
#define GRID   296
#define NSTRIP 64              // 64 A-strips of 128 rows
#define BCHUNKS (((OUT_F*IN_F)+(OUT_F*OUT_F))/4)   // 393216 float4 units

__device__ __align__(16) __half g_A[(size_t)BDIM * K_TOT];
__device__ __align__(16) __half g_B[(size_t)OUT_F * K_TOT];
__device__ uint32_t g_ctr = 0;
__device__ uint32_t g_flagA[NSTRIP];
__device__ uint32_t g_flagB = 0;

__device__ __forceinline__ uint32_t smem_u32(const void* p){
    uint32_t a;
    asm("{ .reg .u64 t; cvta.to.shared.u64 t, %1; cvt.u32.u64 %0, t; }":"=r"(a):"l"(p));
    return a;
}
__device__ __forceinline__ uint64_t gaddr(const void* p){
    uint64_t a; asm("cvta.to.global.u64 %0, %1;":"=l"(a):"l"(p)); return a;
}
__device__ __forceinline__ void cp16(uint32_t dst, uint64_t src){
    asm volatile("cp.async.cg.shared.global [%0], [%1], 16;"::"r"(dst),"l"(src));
}
__device__ __forceinline__ uint32_t ld_acq(const uint32_t* p){
    uint32_t v;
    asm volatile("ld.acquire.gpu.u32 %0, [%1];":"=r"(v):"l"(p):"memory");
    return v;
}
__device__ __forceinline__ uint2 f4_to_h4(float4 f){
    uint2 pk;
    pk.x = (uint32_t)__half_as_ushort(__float2half_rn(f.x)) |
           ((uint32_t)__half_as_ushort(__float2half_rn(f.y))<<16);
    pk.y = (uint32_t)__half_as_ushort(__float2half_rn(f.z)) |
           ((uint32_t)__half_as_ushort(__float2half_rn(f.w))<<16);
    return pk;
}
#define LDSM4(r0,r1,r2,r3,addr) \
    asm volatile("ldmatrix.sync.aligned.m8n8.x4.shared.b16 {%0,%1,%2,%3}, [%4];" \
        : "=r"(r0),"=r"(r1),"=r"(r2),"=r"(r3) : "r"(addr))
#define MMA(d,a,b0,b1) \
    asm volatile("mma.sync.aligned.m16n8k16.row.col.f32.f16.f16.f32 " \
        "{%0,%1,%2,%3}, {%4,%5,%6,%7}, {%8,%9}, {%0,%1,%2,%3};" \
        : "+f"((d)[0]),"+f"((d)[1]),"+f"((d)[2]),"+f"((d)[3]) \
        : "r"((a)[0]),"r"((a)[1]),"r"((a)[2]),"r"((a)[3]),"r"(b0),"r"(b1))

__global__ void __launch_bounds__(256, 2) lsnn_fused(
    const float* __restrict__ spk, const float* __restrict__ zin,
    const float* __restrict__ vin, const float* __restrict__ iin,
    const float* __restrict__ bin, const float* __restrict__ win,
    const float* __restrict__ wrec, float* __restrict__ out)
{
    extern __shared__ char smem_raw[];
    __shared__ uint32_t sh_epoch;
    const uint32_t s0 = (smem_u32(smem_raw) + 1023u) & ~1023u;
    const int tid = threadIdx.x, wid = tid>>5, lane = tid&31;
    const int wm = wid & 3, wn = wid >> 2;
    const int bid = blockIdx.x;

    if (tid == 0) sh_epoch = atomicAdd(&g_ctr, 1u) / GRID;
    __syncthreads();
    const uint32_t epoch = sh_epoch;
    const uint32_t tgtA = (epoch + 1u) * 4u;
    const uint32_t tgtB = (epoch + 1u) * 40u;

    // ================= prep phase (disjoint shares) =================
    if (bid < 256){
        // quarter of A-strip: strip s = bid>>2, rows s*128 + (bid&3)*32 .. +31
        const int R0 = (bid>>2)*128 + (bid&3)*32;
        for (int c = tid; c < 32*384; c += 256){
            const int row = R0 + (c >> 8)/ (384>>8 ? 1 : 1), rr = c / 384, w = c - rr*384;
            const int r = R0 + rr;
            if (w < 128){
                float4 f = *reinterpret_cast<const float4*>(spk + (size_t)r*IN_F + w*4);
                *reinterpret_cast<uint2*>(g_A + (size_t)r*K_TOT + w*4) = f4_to_h4(f);
            } else {
                const int wz = w - 128;
                float4 f = *reinterpret_cast<const float4*>(zin + (size_t)r*OUT_F + wz*4);
                *reinterpret_cast<uint2*>(g_A + (size_t)r*K_TOT + 512 + wz*4) = f4_to_h4(f);
            }
            (void)row;
        }
        __threadfence();
        __syncthreads();
        if (tid == 0) atomicAdd(&g_flagA[bid>>2], 1u);
    } else {
        // 1/40 of B
        for (int c = (bid-256)*256 + tid; c < BCHUNKS; c += 40*256){
            if (c < (OUT_F*IN_F)/4){
                const int o = c >> 7, w = (c & 127) << 2;
                float4 f = *reinterpret_cast<const float4*>(win + (size_t)o*IN_F + w);
                *reinterpret_cast<uint2*>(g_B + (size_t)o*K_TOT + w) = f4_to_h4(f);
            } else {
                const int c2 = c - (OUT_F*IN_F)/4;
                const int o = c2 >> 8, w = (c2 & 255) << 2;
                float4 f = *reinterpret_cast<const float4*>(wrec + (size_t)o*OUT_F + w);
                *reinterpret_cast<uint2*>(g_B + (size_t)o*K_TOT + IN_F + w) = f4_to_h4(f);
            }
        }
        __threadfence();
        __syncthreads();
        if (tid == 0) atomicAdd(&g_flagB, 1u);
    }

    // ================= GEMM phase (R13 persistent loop) =================
    uint32_t dA[8], sAo[8], dB[4], sBo[4];
#pragma unroll
    for (int j = 0; j < 8; j++){
        int ch = tid + j*256, h = ch>>10, idx = ch&1023, r = idx>>3, c = idx&7;
        dA[j]  = (uint32_t)(h*16384 + r*128 + ((c ^ (r&7))<<4));
        sAo[j] = (uint32_t)(r*(K_TOT*2) + h*128 + c*16);
    }
#pragma unroll
    for (int j = 0; j < 4; j++){
        int ch = tid + j*256, h = ch>>9, idx = ch&511, r = idx>>3, c = idx&7;
        dB[j]  = (uint32_t)(h*8192 + r*128 + ((c ^ (r&7))<<4));
        sBo[j] = (uint32_t)(r*(K_TOT*2) + h*128 + c*16);
    }
#define LOAD_STAGE(par, ga, gb, it) do{ \
        const uint32_t _sa = s0 + (par)*A_STAGE; \
        const uint32_t _sb = s0 + SM_B_OFF + (par)*B_STAGE; \
        const uint64_t _ga = (ga) + (uint32_t)((it)*(BK*2)); \
        const uint64_t _gb = (gb) + (uint32_t)((it)*(BK*2)); \
        _Pragma("unroll") \
        for (int _j = 0; _j < 8; _j++) cp16(_sa + dA[_j], _ga + sAo[_j]); \
        _Pragma("unroll") \
        for (int _j = 0; _j < 4; _j++) cp16(_sb + dB[_j], _gb + sBo[_j]); \
    }while(0)

    const int rA = lane & 15, hi = lane >> 4;
    const int arow0 = wm*32 + rA, arow1 = wm*32 + 16 + rA;
    const int brow0 = wn*32 + rA, brow1 = wn*32 + 16 + rA;
    uint32_t offA[2][4], offB[2][4];
#pragma unroll
    for (int k4 = 0; k4 < 4; k4++){
        const int ch = k4*2 + hi;
        offA[0][k4] = (uint32_t)(arow0*128 + ((ch ^ (arow0&7))<<4));
        offA[1][k4] = (uint32_t)(arow1*128 + ((ch ^ (arow1&7))<<4));
        offB[0][k4] = (uint32_t)(brow0*128 + ((ch ^ (brow0&7))<<4));
        offB[1][k4] = (uint32_t)(brow1*128 + ((ch ^ (brow1&7))<<4));
    }

    const float C_VD = 0.1f;
    const float C_ID = -0.2f;
    const float C_BD = 1.25e-6f;
    const float C_BJ = 0.00225f;
    const uint32_t PSB = (uint32_t)(BDIM*OUT_F*4);
    const uint32_t colb0 = (uint32_t)((wn*32 + 2*(lane&3)) * 4);
    const uint64_t gAbase = gaddr(g_A), gBbase = gaddr(g_B);

    const int tile0 = bid;
    uint64_t gAc = gAbase + (uint64_t)((tile0>>4)*BM)*(K_TOT*2);
    uint64_t gBc = gBbase + (uint64_t)((tile0&15)*BN)*(K_TOT*2);

    // wait for first tile's A-strip + all of B (all threads spin; converges)
    while (ld_acq(&g_flagA[tile0>>4]) < tgtA) {}
    while (ld_acq(&g_flagB) < tgtB) {}
    LOAD_STAGE(0, gAc, gBc, 0);
    asm volatile("cp.async.commit_group;":::"memory");

    for (int t = tile0; t < NTILES; t += GRID){
        const int m0 = (t>>4)*BM, n0 = (t&15)*BN;
        const int tn = t + GRID;
        const bool hn = (tn < NTILES);
        const uint64_t gAn = hn ? gAbase + (uint64_t)((tn>>4)*BM)*(K_TOT*2) : 0;
        const uint64_t gBn = hn ? gBbase + (uint64_t)((tn&15)*BN)*(K_TOT*2) : 0;

        float acc[2][4][4];
#pragma unroll
        for (int a = 0; a < 2; a++)
#pragma unroll
            for (int b = 0; b < 4; b++)
#pragma unroll
                for (int c = 0; c < 4; c++) acc[a][b][c] = 0.0f;

        for (int i = 0; i < NIT; i++){
            asm volatile("cp.async.wait_group 0;":::"memory");
            __syncthreads();

            if (i + 1 < NIT)      LOAD_STAGE((i+1)&1, gAc, gBc, i+1);
            else if (hn){
                while (ld_acq(&g_flagA[tn>>4]) < tgtA) {}   // nearly always ready
                LOAD_STAGE(0, gAn, gBn, 0);
            }
            asm volatile("cp.async.commit_group;":::"memory");

            const uint32_t aB = s0 + (i&1)*A_STAGE;
            const uint32_t bB = s0 + SM_B_OFF + (i&1)*B_STAGE;

            uint32_t a[2][2][4], b[2][2][4];
            LDSM4(a[0][0][0],a[0][0][1],a[0][0][2],a[0][0][3], aB + offA[0][0]);
            LDSM4(a[0][1][0],a[0][1][1],a[0][1][2],a[0][1][3], aB + offA[1][0]);
            LDSM4(b[0][0][0],b[0][0][1],b[0][0][2],b[0][0][3], bB + offB[0][0]);
            LDSM4(b[0][1][0],b[0][1][1],b[0][1][2],b[0][1][3], bB + offB[1][0]);
#pragma unroll
            for (int kk = 0; kk < 8; kk++){
                const int cur = kk & 1, nxt = cur ^ 1;
                if (kk < 7){
                    const int kn = kk + 1;
                    const uint32_t ha = (kn >> 2) ? 16384u : 0u;
                    const uint32_t hb = (kn >> 2) ? 8192u  : 0u;
                    LDSM4(a[nxt][0][0],a[nxt][0][1],a[nxt][0][2],a[nxt][0][3],
                          aB + ha + offA[0][kn&3]);
                    LDSM4(a[nxt][1][0],a[nxt][1][1],a[nxt][1][2],a[nxt][1][3],
                          aB + ha + offA[1][kn&3]);
                    LDSM4(b[nxt][0][0],b[nxt][0][1],b[nxt][0][2],b[nxt][0][3],
                          bB + hb + offB[0][kn&3]);
                    LDSM4(b[nxt][1][0],b[nxt][1][1],b[nxt][1][2],b[nxt][1][3],
                          bB + hb + offB[1][kn&3]);
                }
#pragma unroll
                for (int tt = 0; tt < 2; tt++)
#pragma unroll
                    for (int n8 = 0; n8 < 4; n8++)
                        MMA(acc[tt][n8], a[cur][tt],
                            b[cur][n8>>1][n8&1], b[cur][n8>>1][(n8&1)+2]);
            }
        }

        const uint32_t colb = colb0 + (uint32_t)(n0*4);
#pragma unroll
        for (int tt = 0; tt < 2; tt++){
#pragma unroll
            for (int rr = 0; rr < 2; rr++){
                const uint32_t ro = ((uint32_t)(m0 + wm*32 + tt*16 + rr*8 + (lane>>2)) << 12)
                                    + colb;
                const char* vb  = (const char*)vin + ro;
                const char* ib  = (const char*)iin + ro;
                const char* bb_ = (const char*)bin + ro;
                char* ob = (char*)out + ro;
#pragma unroll
                for (int n8 = 0; n8 < 4; n8++){
                    const uint32_t co = (uint32_t)(n8*32);
                    float2 v2 = *reinterpret_cast<const float2*>(vb + co);
                    float2 i2 = *reinterpret_cast<const float2*>(ib + co);
                    float2 b2 = *reinterpret_cast<const float2*>(bb_ + co);
                    float vv[2] = {v2.x, v2.y}, ii[2] = {i2.x, i2.y}, bbv[2] = {b2.x, b2.y};
                    float zz[2], vo[2], io[2], bo[2];
#pragma unroll
                    for (int e = 0; e < 2; e++){
                        float vd = __fadd_rn(vv[e], __fmul_rn(C_VD, __fadd_rn(ii[e], -vv[e])));
                        float id = __fadd_rn(ii[e], __fmul_rn(C_ID, ii[e]));
                        float bd = __fadd_rn(bbv[e], __fmul_rn(C_BD, __fadd_rn(1.0f, -bbv[e])));
                        float zn = (__fadd_rn(vd, -bd) > 0.0f) ? 1.0f : 0.0f;
                        zz[e] = zn;
                        vo[e] = (zn != 0.0f) ? 0.0f : vd;
                        io[e] = __fadd_rn(id, acc[tt][n8][rr*2 + e]);
                        bo[e] = __fadd_rn(bd, __fmul_rn(zn, C_BJ));
                    }
                    *reinterpret_cast<float2*>(ob + co)           = make_float2(zz[0], zz[1]);
                    *reinterpret_cast<float2*>(ob + PSB + co)     = make_float2(vo[0], vo[1]);
                    *reinterpret_cast<float2*>(ob + 2u*PSB + co)  = make_float2(io[0], io[1]);
                    *reinterpret_cast<float2*>(ob + 3u*PSB + co)  = make_float2(bo[0], bo[1]);
                }
            }
        }

        gAc = gAn; gBc = gBn;
    }
}

extern "C" void kernel_launch(void* const* d_in, const int* in_sizes, int n_in,
                              void* d_out, int out_size){
    const float* spikes = (const float*)d_in[0];
    const float* z      = (const float*)d_in[1];
    const float* v      = (const float*)d_in[2];
    const float* i_     = (const float*)d_in[3];
    const float* b      = (const float*)d_in[4];
    const float* win    = (const float*)d_in[5];
    const float* wrec   = (const float*)d_in[6];
    float* out = (float*)d_out;

    cudaFuncSetAttribute(lsnn_fused, cudaFuncAttributeMaxDynamicSharedMemorySize, SMEM_DYN);
    lsnn_fused<<<GRID, 256, SMEM_DYN>>>(spikes, z, v, i_, b, win, wrec, out);
}

// round 15
// speedup vs baseline: 1.1632x; 1.1632x over previous
#include <cuda_runtime.h>
#include <cuda_fp16.h>
#include <cstdint>

#define BDIM   8192
#define IN_F   512
#define OUT_F  1024
#define K_TOT  1536
#define BM 128
#define BN 128
#define BK 64
#define NIT (K_TOT/BK)         // 24
#define STG 16384              // one A or B stage (128 rows x 128B)
#define SM_B_OFF (3*STG)
#define SMEM_DYN (6*STG + 1024)  // 99328 -> 2 CTAs/SM
#define NTILES 512             // 64 m-tiles x 8 n-tiles
#define GRID   296

__device__ __align__(16) __half g_A[(size_t)BDIM * K_TOT];
__device__ __align__(16) __half g_B[(size_t)OUT_F * K_TOT];

__device__ __forceinline__ uint32_t smem_u32(const void* p){
    uint32_t a;
    asm("{ .reg .u64 t; cvta.to.shared.u64 t, %1; cvt.u32.u64 %0, t; }":"=r"(a):"l"(p));
    return a;
}
__device__ __forceinline__ uint64_t gaddr(const void* p){
    uint64_t a; asm("cvta.to.global.u64 %0, %1;":"=l"(a):"l"(p)); return a;
}
__device__ __forceinline__ void cp16(uint32_t dst, uint64_t src){
    asm volatile("cp.async.cg.shared.global [%0], [%1], 16;"::"r"(dst),"l"(src));
}
__device__ __forceinline__ uint2 f4_to_h4(float4 f){
    uint2 pk;
    pk.x = (uint32_t)__half_as_ushort(__float2half_rn(f.x)) |
           ((uint32_t)__half_as_ushort(__float2half_rn(f.y))<<16);
    pk.y = (uint32_t)__half_as_ushort(__float2half_rn(f.z)) |
           ((uint32_t)__half_as_ushort(__float2half_rn(f.w))<<16);
    return pk;
}
#define LDSM4(r0,r1,r2,r3,addr) \
    asm volatile("ldmatrix.sync.aligned.m8n8.x4.shared.b16 {%0,%1,%2,%3}, [%4];" \
        : "=r"(r0),"=r"(r1),"=r"(r2),"=r"(r3) : "r"(addr))
#define MMA(d,a,b0,b1) \
    asm volatile("mma.sync.aligned.m16n8k16.row.col.f32.f16.f16.f32 " \
        "{%0,%1,%2,%3}, {%4,%5,%6,%7}, {%8,%9}, {%0,%1,%2,%3};" \
        : "+f"((d)[0]),"+f"((d)[1]),"+f"((d)[2]),"+f"((d)[3]) \
        : "r"((a)[0]),"r"((a)[1]),"r"((a)[2]),"r"((a)[3]),"r"(b0),"r"(b1))

// ---- merged prep: A=[spk|z] fp16 (binary, exact); B=[Win|Wrec] fp16 ----
#define T_SPK (BDIM*(IN_F/4))
#define T_Z   (BDIM*(OUT_F/4))
#define T_WIN ((OUT_F*IN_F)/4)
#define T_WRC ((OUT_F*OUT_F)/4)
#define T_ALL (T_SPK+T_Z+T_WIN+T_WRC)

__global__ void prep_all(const float* __restrict__ spk, const float* __restrict__ zin,
                         const float* __restrict__ win, const float* __restrict__ wrec){
    int t = blockIdx.x*blockDim.x + threadIdx.x;
    if (t < T_SPK){
        int row = t>>7, c = (t&127)<<2;
        float4 f = *reinterpret_cast<const float4*>(spk + (size_t)row*IN_F + c);
        *reinterpret_cast<uint2*>(g_A + (size_t)row*K_TOT + c) = f4_to_h4(f);
    } else if (t < T_SPK + T_Z){
        int t2 = t - T_SPK;
        int row = t2>>8, c = (t2&255)<<2;
        float4 f = *reinterpret_cast<const float4*>(zin + (size_t)row*OUT_F + c);
        *reinterpret_cast<uint2*>(g_A + (size_t)row*K_TOT + IN_F + c) = f4_to_h4(f);
    } else if (t < T_SPK + T_Z + T_WIN){
        int t2 = t - (T_SPK + T_Z);
        int o = t2>>7, c = (t2&127)<<2;
        float4 f = *reinterpret_cast<const float4*>(win + (size_t)o*IN_F + c);
        *reinterpret_cast<uint2*>(g_B + (size_t)o*K_TOT + c) = f4_to_h4(f);
    } else {
        int t2 = t - (T_SPK + T_Z + T_WIN);
        if (t2 < T_WRC){
            int o = t2>>8, c = (t2&255)<<2;
            float4 f = *reinterpret_cast<const float4*>(wrec + (size_t)o*OUT_F + c);
            *reinterpret_cast<uint2*>(g_B + (size_t)o*K_TOT + IN_F + c) = f4_to_h4(f);
        }
    }
}

__global__ void __launch_bounds__(256, 2) lsnn_gemm(
    const float* __restrict__ vin, const float* __restrict__ iin,
    const float* __restrict__ bin, float* __restrict__ out)
{
    extern __shared__ char smem_raw[];
    const uint32_t s0 = (smem_u32(smem_raw) + 1023u) & ~1023u;
    const int tid = threadIdx.x, wid = tid>>5, lane = tid&31;
    const int wm = wid & 1, wn = wid >> 1;      // 2m x 4n warp grid (64m x 32n tiles)
    const uint64_t gAbase = gaddr(g_A), gBbase = gaddr(g_B);

    // loader: A and B stages have identical geometry (128 rows x 128B)
#define LOAD_STAGE(st, ao, bo, ki) do{ \
        const uint32_t _sa = s0 + (st)*STG; \
        const uint32_t _sb = s0 + SM_B_OFF + (st)*STG; \
        const uint64_t _ga = gAbase + (ao) + (uint32_t)((ki)*128); \
        const uint64_t _gb = gBbase + (bo) + (uint32_t)((ki)*128); \
        _Pragma("unroll") \
        for (int _j = 0; _j < 4; _j++){ \
            int _ch = tid + _j*256, _r = _ch>>3, _c = _ch&7; \
            uint32_t _sw = (uint32_t)(_r*128 + ((_c ^ (_r&7))<<4)); \
            uint32_t _go = (uint32_t)(_r*(K_TOT*2) + _c*16); \
            cp16(_sa + _sw, _ga + _go); \
            cp16(_sb + _sw, _gb + _go); \
        } \
    }while(0)

    const int rA = lane & 15;
    const uint32_t hi16 = (uint32_t)((lane >> 4) << 4);
    // base row offsets; higher frag rows differ by multiples of 8 -> +mt*2048
    const int arow0 = wm*64 + rA;
    const int brow0 = wn*32 + rA;
    const uint32_t roA0 = (uint32_t)(arow0*128 + ((rA&7)<<4));
    const uint32_t roB0 = (uint32_t)(brow0*128 + ((rA&7)<<4));

    const float C_VD = 0.1f;
    const float C_ID = -0.2f;
    const float C_BD = 1.25e-6f;
    const float C_BJ = 0.00225f;
    const uint32_t PSB = (uint32_t)(BDIM*OUT_F*4);
    const uint32_t colb0 = (uint32_t)((wn*32 + 2*(lane&3)) * 4);

    // ---- persistent + lookahead-2 pipeline ----
    const int tile0 = blockIdx.x;
    if (tile0 >= NTILES) return;
    int lt = tile0, li = 0;
    uint32_t aoff = (uint32_t)((lt>>3)*BM)*(K_TOT*2);
    uint32_t boff = (uint32_t)((lt&7)*BN)*(K_TOT*2);
#define ADV() do{ if(++li==NIT){ li=0; lt+=GRID; if(lt<NTILES){ \
        aoff=(uint32_t)((lt>>3)*BM)*(K_TOT*2); boff=(uint32_t)((lt&7)*BN)*(K_TOT*2);} } }while(0)

    LOAD_STAGE(0, aoff, boff, li);
    asm volatile("cp.async.commit_group;":::"memory");
    ADV();
    LOAD_STAGE(1, aoff, boff, li);
    asm volatile("cp.async.commit_group;":::"memory");
    ADV();

    int sc = 0;
    for (int t = tile0; t < NTILES; t += GRID){
        const int m0 = (t>>3)*BM, n0 = (t&7)*BN;

        float acc[4][4][4];
#pragma unroll
        for (int x = 0; x < 4; x++)
#pragma unroll
            for (int y = 0; y < 4; y++)
#pragma unroll
                for (int c = 0; c < 4; c++) acc[x][y][c] = 0.0f;

        for (int i = 0; i < NIT; i++){
            asm volatile("cp.async.wait_group 1;":::"memory");   // stage sc arrived
            __syncthreads();   // publish; all warps done with the stage being reloaded

            if (lt < NTILES){
                int s2 = sc + 2; if (s2 >= 3) s2 -= 3;
                LOAD_STAGE(s2, aoff, boff, li);
                ADV();
            }
            asm volatile("cp.async.commit_group;":::"memory");

            const uint32_t aB = s0 + sc*STG;
            const uint32_t bB = s0 + SM_B_OFF + sc*STG;
            const uint32_t adA0 = (aB + roA0) ^ hi16;
            const uint32_t adB0 = (bB + roB0) ^ hi16;

            uint32_t a[2][4][4], b[2][4];
#pragma unroll
            for (int mt = 0; mt < 4; mt++)       // preload A kk=0
                LDSM4(a[0][mt][0],a[0][mt][1],a[0][mt][2],a[0][mt][3],
                      adA0 + mt*2048);
#pragma unroll
            for (int kk = 0; kk < 4; kk++){
                const int cur = kk & 1, nxt = cur ^ 1;
                LDSM4(b[0][0],b[0][1],b[0][2],b[0][3], (adB0 ^ (kk<<5)));
                LDSM4(b[1][0],b[1][1],b[1][2],b[1][3], (adB0 ^ (kk<<5)) + 2048);
                if (kk < 3){
#pragma unroll
                    for (int mt = 0; mt < 4; mt++)
                        LDSM4(a[nxt][mt][0],a[nxt][mt][1],a[nxt][mt][2],a[nxt][mt][3],
                              (adA0 ^ ((kk+1)<<5)) + mt*2048);
                }
#pragma unroll
                for (int mt = 0; mt < 4; mt++)
#pragma unroll
                    for (int n8 = 0; n8 < 4; n8++)
                        MMA(acc[mt][n8], a[cur][mt],
                            b[n8>>1][n8&1], b[n8>>1][(n8&1)+2]);
            }
            if (++sc == 3) sc = 0;
        }

        // ---- fused epilogue (next tile's stages already in flight) ----
        const uint32_t colb = colb0 + (uint32_t)(n0*4);
#pragma unroll
        for (int mt = 0; mt < 4; mt++){
#pragma unroll
            for (int rr = 0; rr < 2; rr++){
                const uint32_t ro = ((uint32_t)(m0 + wm*64 + mt*16 + rr*8 + (lane>>2)) << 12)
                                    + colb;
                const char* vb  = (const char*)vin + ro;
                const char* ib  = (const char*)iin + ro;
                const char* bb_ = (const char*)bin + ro;
                char* ob = (char*)out + ro;
#pragma unroll
                for (int n8 = 0; n8 < 4; n8++){
                    const uint32_t co = (uint32_t)(n8*32);
                    float2 v2 = *reinterpret_cast<const float2*>(vb + co);
                    float2 i2 = *reinterpret_cast<const float2*>(ib + co);
                    float2 b2 = *reinterpret_cast<const float2*>(bb_ + co);
                    float vv[2] = {v2.x, v2.y}, ii[2] = {i2.x, i2.y}, bbv[2] = {b2.x, b2.y};
                    float zz[2], vo[2], io[2], bo[2];
#pragma unroll
                    for (int e = 0; e < 2; e++){
                        float vd = __fadd_rn(vv[e], __fmul_rn(C_VD, __fadd_rn(ii[e], -vv[e])));
                        float id = __fadd_rn(ii[e], __fmul_rn(C_ID, ii[e]));
                        float bd = __fadd_rn(bbv[e], __fmul_rn(C_BD, __fadd_rn(1.0f, -bbv[e])));
                        float zn = (__fadd_rn(vd, -bd) > 0.0f) ? 1.0f : 0.0f;
                        zz[e] = zn;
                        vo[e] = (zn != 0.0f) ? 0.0f : vd;
                        io[e] = __fadd_rn(id, acc[mt][n8][rr*2 + e]);
                        bo[e] = __fadd_rn(bd, __fmul_rn(zn, C_BJ));
                    }
                    *reinterpret_cast<float2*>(ob + co)           = make_float2(zz[0], zz[1]);
                    *reinterpret_cast<float2*>(ob + PSB + co)     = make_float2(vo[0], vo[1]);
                    *reinterpret_cast<float2*>(ob + 2u*PSB + co)  = make_float2(io[0], io[1]);
                    *reinterpret_cast<float2*>(ob + 3u*PSB + co)  = make_float2(bo[0], bo[1]);
                }
            }
        }
    }
}

extern "C" void kernel_launch(void* const* d_in, const int* in_sizes, int n_in,
                              void* d_out, int out_size){
    const float* spikes = (const float*)d_in[0];
    const float* z      = (const float*)d_in[1];
    const float* v      = (const float*)d_in[2];
    const float* i_     = (const float*)d_in[3];
    const float* b      = (const float*)d_in[4];
    const float* win    = (const float*)d_in[5];
    const float* wrec   = (const float*)d_in[6];
    float* out = (float*)d_out;

    cudaFuncSetAttribute(lsnn_gemm, cudaFuncAttributeMaxDynamicSharedMemorySize, SMEM_DYN);

    prep_all<<<(T_ALL + 255)/256, 256>>>(spikes, z, win, wrec);
    lsnn_gemm<<<GRID, 256, SMEM_DYN>>>(v, i_, b, out);
}

// round 16
// speedup vs baseline: 1.2315x; 1.0587x over previous
#include <cuda_runtime.h>
#include <cuda_fp16.h>
#include <cstdint>

#define BDIM   8192
#define IN_F   512
#define OUT_F  1024
#define K_TOT  1536
#define BM 128
#define BN 64
#define BK 128
#define NIT (K_TOT/BK)         // 12
#define A_STAGE 32768
#define B_STAGE 16384
#define SM_B_OFF (2*A_STAGE)
#define SMEM_DYN (2*A_STAGE + 2*B_STAGE + 1024)
#define GRID   296
#define NT_FULL 888            // 296*3 full tiles; remaining 136 tiles split in M

__device__ __align__(16) __half g_A[(size_t)BDIM * K_TOT];
__device__ __align__(16) __half g_B[(size_t)OUT_F * K_TOT];

__device__ __forceinline__ uint32_t smem_u32(const void* p){
    uint32_t a;
    asm("{ .reg .u64 t; cvta.to.shared.u64 t, %1; cvt.u32.u64 %0, t; }":"=r"(a):"l"(p));
    return a;
}
__device__ __forceinline__ uint64_t gaddr(const void* p){
    uint64_t a; asm("cvta.to.global.u64 %0, %1;":"=l"(a):"l"(p)); return a;
}
__device__ __forceinline__ void cp16(uint32_t dst, uint64_t src){
    asm volatile("cp.async.cg.shared.global [%0], [%1], 16;"::"r"(dst),"l"(src));
}
__device__ __forceinline__ uint2 f4_to_h4(float4 f){
    uint2 pk;
    pk.x = (uint32_t)__half_as_ushort(__float2half_rn(f.x)) |
           ((uint32_t)__half_as_ushort(__float2half_rn(f.y))<<16);
    pk.y = (uint32_t)__half_as_ushort(__float2half_rn(f.z)) |
           ((uint32_t)__half_as_ushort(__float2half_rn(f.w))<<16);
    return pk;
}
#define LDSM4(r0,r1,r2,r3,addr) \
    asm volatile("ldmatrix.sync.aligned.m8n8.x4.shared.b16 {%0,%1,%2,%3}, [%4];" \
        : "=r"(r0),"=r"(r1),"=r"(r2),"=r"(r3) : "r"(addr))
#define MMA(d,a,b0,b1) \
    asm volatile("mma.sync.aligned.m16n8k16.row.col.f32.f16.f16.f32 " \
        "{%0,%1,%2,%3}, {%4,%5,%6,%7}, {%8,%9}, {%0,%1,%2,%3};" \
        : "+f"((d)[0]),"+f"((d)[1]),"+f"((d)[2]),"+f"((d)[3]) \
        : "r"((a)[0]),"r"((a)[1]),"r"((a)[2]),"r"((a)[3]),"r"(b0),"r"(b1))

#define T_SPK (BDIM*(IN_F/4))
#define T_Z   (BDIM*(OUT_F/4))
#define T_WIN ((OUT_F*IN_F)/4)
#define T_WRC ((OUT_F*OUT_F)/4)
#define T_ALL (T_SPK+T_Z+T_WIN+T_WRC)

__global__ void prep_all(const float* __restrict__ spk, const float* __restrict__ zin,
                         const float* __restrict__ win, const float* __restrict__ wrec){
    int t = blockIdx.x*blockDim.x + threadIdx.x;
    if (t < T_SPK){
        int row = t>>7, c = (t&127)<<2;
        float4 f = *reinterpret_cast<const float4*>(spk + (size_t)row*IN_F + c);
        *reinterpret_cast<uint2*>(g_A + (size_t)row*K_TOT + c) = f4_to_h4(f);
    } else if (t < T_SPK + T_Z){
        int t2 = t - T_SPK;
        int row = t2>>8, c = (t2&255)<<2;
        float4 f = *reinterpret_cast<const float4*>(zin + (size_t)row*OUT_F + c);
        *reinterpret_cast<uint2*>(g_A + (size_t)row*K_TOT + IN_F + c) = f4_to_h4(f);
    } else if (t < T_SPK + T_Z + T_WIN){
        int t2 = t - (T_SPK + T_Z);
        int o = t2>>7, c = (t2&127)<<2;
        float4 f = *reinterpret_cast<const float4*>(win + (size_t)o*IN_F + c);
        *reinterpret_cast<uint2*>(g_B + (size_t)o*K_TOT + c) = f4_to_h4(f);
    } else {
        int t2 = t - (T_SPK + T_Z + T_WIN);
        if (t2 < T_WRC){
            int o = t2>>8, c = (t2&255)<<2;
            float4 f = *reinterpret_cast<const float4*>(wrec + (size_t)o*OUT_F + c);
            *reinterpret_cast<uint2*>(g_B + (size_t)o*K_TOT + IN_F + c) = f4_to_h4(f);
        }
    }
}

__global__ void __launch_bounds__(256, 2) lsnn_gemm(
    const float* __restrict__ vin, const float* __restrict__ iin,
    const float* __restrict__ bin, float* __restrict__ out)
{
    extern __shared__ char smem_raw[];
    const uint32_t s0 = (smem_u32(smem_raw) + 1023u) & ~1023u;
    const int tid = threadIdx.x, wid = tid>>5, lane = tid&31;
    const int bid = blockIdx.x;
    const uint64_t gAbase = gaddr(g_A), gBbase = gaddr(g_B);
    const int njobs = (bid < 272) ? 4 : 3;

    // loader: rows = 128 (full) or 64 (half job; A-rows predicated)
#define LOAD_STAGE(par, ao, bo, ki, rows) do{ \
        const uint32_t _sa = s0 + (par)*A_STAGE; \
        const uint32_t _sb = s0 + SM_B_OFF + (par)*B_STAGE; \
        const uint64_t _ga = gAbase + (ao) + (uint32_t)((ki)*(BK*2)); \
        const uint64_t _gb = gBbase + (bo) + (uint32_t)((ki)*(BK*2)); \
        _Pragma("unroll") \
        for (int _j = 0; _j < 8; _j++){ \
            int _ch = tid + _j*256, _h = _ch>>10, _i = _ch&1023, _r = _i>>3, _c = _i&7; \
            if (_r < (rows)){ \
                uint32_t _sw = (uint32_t)(_h*16384 + _r*128 + ((_c ^ (_r&7))<<4)); \
                cp16(_sa + _sw, _ga + (uint32_t)(_r*(K_TOT*2) + _h*128 + _c*16)); } } \
        _Pragma("unroll") \
        for (int _j = 0; _j < 4; _j++){ \
            int _ch = tid + _j*256, _h = _ch>>9, _i = _ch&511, _r = _i>>3, _c = _i&7; \
            uint32_t _sw = (uint32_t)(_h*8192 + _r*128 + ((_c ^ (_r&7))<<4)); \
            cp16(_sb + _sw, _gb + (uint32_t)(_r*(K_TOT*2) + _h*128 + _c*16)); } \
    }while(0)

    // job geometry: j<3 -> full tile bid+296j ; j==3 -> M-half of tile 888+(bid>>1)
#define JOB_GEOM(j, m0_, n0_, rows_) do{ \
        if ((j) < 3){ int _t = bid + 296*(j); (m0_)=(_t>>4)*BM; (n0_)=(_t&15)*BN; (rows_)=128; } \
        else { int _th = NT_FULL + (bid>>1); \
               (m0_)=(_th>>4)*BM + (bid&1)*64; (n0_)=(_th&15)*BN; (rows_)=64; } \
    }while(0)

    const int rA = lane & 15;
    const uint32_t hi16 = (uint32_t)((lane >> 4) << 4);
    const float C_VD = 0.1f;
    const float C_ID = -0.2f;
    const float C_BD = 1.25e-6f;
    const float C_BJ = 0.00225f;
    const uint32_t PSB = (uint32_t)(BDIM*OUT_F*4);

    // prologue: job 0 stage 0
    {
        int m0p, n0p, rp; JOB_GEOM(0, m0p, n0p, rp);
        LOAD_STAGE(0, (uint32_t)m0p*(K_TOT*2), (uint32_t)n0p*(K_TOT*2), 0, rp);
    }
    asm volatile("cp.async.commit_group;":::"memory");

    for (int j = 0; j < njobs; j++){
        int m0, n0, rows; JOB_GEOM(j, m0, n0, rows);
        const bool full = (rows == 128);
        const bool active = full || (wid < 4);
        const uint32_t aoC = (uint32_t)m0*(K_TOT*2), boC = (uint32_t)n0*(K_TOT*2);
        // per-job warp mapping: full 4m x 2n ; half 2m x 2n on warps 0-3
        const int mwarp = (full ? (wid & 3) : (wid & 1)) * 32;
        const int nwarp = (full ? (wid >> 2) : ((wid >> 1) & 1)) * 32;
        const int a0row = mwarp + rA, b0row = nwarp + rA;
        const uint32_t roA0 = (uint32_t)(a0row*128 + ((a0row&7)<<4));
        const uint32_t roB0 = (uint32_t)(b0row*128 + ((b0row&7)<<4));

        float acc[2][4][4];
#pragma unroll
        for (int x = 0; x < 2; x++)
#pragma unroll
            for (int y = 0; y < 4; y++)
#pragma unroll
                for (int c = 0; c < 4; c++) acc[x][y][c] = 0.0f;

        for (int i = 0; i < NIT; i++){
            asm volatile("cp.async.wait_group 0;":::"memory");
            __syncthreads();

            if (i + 1 < NIT){
                LOAD_STAGE((i+1)&1, aoC, boC, i+1, rows);
            } else if (j + 1 < njobs){
                int m0n, n0n, rn; JOB_GEOM(j+1, m0n, n0n, rn);
                LOAD_STAGE(0, (uint32_t)m0n*(K_TOT*2), (uint32_t)n0n*(K_TOT*2), 0, rn);
            }
            asm volatile("cp.async.commit_group;":::"memory");

            if (active){
                const uint32_t aB = s0 + (i&1)*A_STAGE;
                const uint32_t bB = s0 + SM_B_OFF + (i&1)*B_STAGE;
                const uint32_t adA = (aB + roA0) ^ hi16;
                const uint32_t adB = (bB + roB0) ^ hi16;

                uint32_t a[2][2][4], b[2][2][4];
                LDSM4(a[0][0][0],a[0][0][1],a[0][0][2],a[0][0][3], adA);
                LDSM4(a[0][1][0],a[0][1][1],a[0][1][2],a[0][1][3], adA + 2048);
                LDSM4(b[0][0][0],b[0][0][1],b[0][0][2],b[0][0][3], adB);
                LDSM4(b[0][1][0],b[0][1][1],b[0][1][2],b[0][1][3], adB + 2048);
#pragma unroll
                for (int kk = 0; kk < 8; kk++){
                    const int cur = kk & 1, nxt = cur ^ 1;
                    if (kk < 7){
                        const int kn = kk + 1;
                        const uint32_t ha = (kn >> 2) ? 16384u : 0u;
                        const uint32_t hb = (kn >> 2) ? 8192u  : 0u;
                        const uint32_t xk = (uint32_t)((kn & 3) << 5);
                        LDSM4(a[nxt][0][0],a[nxt][0][1],a[nxt][0][2],a[nxt][0][3],
                              (adA ^ xk) + ha);
                        LDSM4(a[nxt][1][0],a[nxt][1][1],a[nxt][1][2],a[nxt][1][3],
                              (adA ^ xk) + ha + 2048);
                        LDSM4(b[nxt][0][0],b[nxt][0][1],b[nxt][0][2],b[nxt][0][3],
                              (adB ^ xk) + hb);
                        LDSM4(b[nxt][1][0],b[nxt][1][1],b[nxt][1][2],b[nxt][1][3],
                              (adB ^ xk) + hb + 2048);
                    }
#pragma unroll
                    for (int tt = 0; tt < 2; tt++)
#pragma unroll
                        for (int n8 = 0; n8 < 4; n8++)
                            MMA(acc[tt][n8], a[cur][tt],
                                b[cur][n8>>1][n8&1], b[cur][n8>>1][(n8&1)+2]);
                }
            }
        }

        if (active){
            const uint32_t colb = (uint32_t)((n0 + nwarp + 2*(lane&3)) * 4);
#pragma unroll
            for (int tt = 0; tt < 2; tt++){
#pragma unroll
                for (int rr = 0; rr < 2; rr++){
                    const uint32_t ro = ((uint32_t)(m0 + mwarp + tt*16 + rr*8 + (lane>>2)) << 12)
                                        + colb;
                    const char* vb  = (const char*)vin + ro;
                    const char* ib  = (const char*)iin + ro;
                    const char* bb_ = (const char*)bin + ro;
                    char* ob = (char*)out + ro;
#pragma unroll
                    for (int n8 = 0; n8 < 4; n8++){
                        const uint32_t co = (uint32_t)(n8*32);
                        float2 v2 = *reinterpret_cast<const float2*>(vb + co);
                        float2 i2 = *reinterpret_cast<const float2*>(ib + co);
                        float2 b2 = *reinterpret_cast<const float2*>(bb_ + co);
                        float vv[2] = {v2.x, v2.y}, ii[2] = {i2.x, i2.y}, bbv[2] = {b2.x, b2.y};
                        float zz[2], vo[2], io[2], bo[2];
#pragma unroll
                        for (int e = 0; e < 2; e++){
                            float vd = __fadd_rn(vv[e], __fmul_rn(C_VD, __fadd_rn(ii[e], -vv[e])));
                            float id = __fadd_rn(ii[e], __fmul_rn(C_ID, ii[e]));
                            float bd = __fadd_rn(bbv[e], __fmul_rn(C_BD, __fadd_rn(1.0f, -bbv[e])));
                            float zn = (__fadd_rn(vd, -bd) > 0.0f) ? 1.0f : 0.0f;
                            zz[e] = zn;
                            vo[e] = (zn != 0.0f) ? 0.0f : vd;
                            io[e] = __fadd_rn(id, acc[tt][n8][rr*2 + e]);
                            bo[e] = __fadd_rn(bd, __fmul_rn(zn, C_BJ));
                        }
                        *reinterpret_cast<float2*>(ob + co)           = make_float2(zz[0], zz[1]);
                        *reinterpret_cast<float2*>(ob + PSB + co)     = make_float2(vo[0], vo[1]);
                        *reinterpret_cast<float2*>(ob + 2u*PSB + co)  = make_float2(io[0], io[1]);
                        *reinterpret_cast<float2*>(ob + 3u*PSB + co)  = make_float2(bo[0], bo[1]);
                    }
                }
            }
        }
    }
}

extern "C" void kernel_launch(void* const* d_in, const int* in_sizes, int n_in,
                              void* d_out, int out_size){
    const float* spikes = (const float*)d_in[0];
    const float* z      = (const float*)d_in[1];
    const float* v      = (const float*)d_in[2];
    const float* i_     = (const float*)d_in[3];
    const float* b      = (const float*)d_in[4];
    const float* win    = (const float*)d_in[5];
    const float* wrec   = (const float*)d_in[6];
    float* out = (float*)d_out;

    cudaFuncSetAttribute(lsnn_gemm, cudaFuncAttributeMaxDynamicSharedMemorySize, SMEM_DYN);

    prep_all<<<(T_ALL + 255)/256, 256>>>(spikes, z, win, wrec);
    lsnn_gemm<<<GRID, 256, SMEM_DYN>>>(v, i_, b, out);
}